// round 16
// baseline (speedup 1.0000x reference)
#include <cuda_runtime.h>
#include <cuda_fp16.h>
#include <stdint.h>
#include <math.h>

#define BATCH 4
#define SEQ   2048
#define CDIM  768
#define NHEAD 12
#define HDIM  64
#define MROWS (BATCH*SEQ)      // 8192
#define QKVO  (3*CDIM)         // 2304
#define KDIM  768
#define KCH   64               // K-chunk (fp16 cols) per gemm pipeline stage
#define NCH   (KDIM/KCH)       // 12
#define TQ    128              // query rows per attention CTA
#define RSB   144              // attention smem row stride bytes
#define GRS   144              // gemm smem row stride bytes (128B data + pad)
#define ASTG  18432            // attention stage (Kh|V)

// q pre-scale: 1/sqrt(64) * log2(e)  -> S-MMA emits log2-domain logits
#define QSCALE 0.180336879f

// Scratch (device globals; ONLY referenced from device code).
__device__ __align__(16) __half g_q [BATCH*NHEAD*SEQ*HDIM];
__device__ __align__(16) __half g_k [BATCH*NHEAD*SEQ*HDIM];
__device__ __align__(16) __half g_v [BATCH*NHEAD*SEQ*HDIM];
__device__ __align__(16) __half g_x [MROWS*CDIM];
__device__ __align__(16) __half g_wq[QKVO*CDIM];
__device__ __align__(16) __half g_wp[CDIM*CDIM];
__device__ __align__(16) __half g_att[MROWS*CDIM];

// ---------------------------------------------------------------------------
__device__ __forceinline__ void mma16816h(float c[4], const uint32_t a[4],
                                          const uint32_t b[2]) {
    asm volatile(
        "mma.sync.aligned.m16n8k16.row.col.f32.f16.f16.f32 "
        "{%0,%1,%2,%3}, {%4,%5,%6,%7}, {%8,%9}, {%0,%1,%2,%3};"
        : "+f"(c[0]), "+f"(c[1]), "+f"(c[2]), "+f"(c[3])
        : "r"(a[0]), "r"(a[1]), "r"(a[2]), "r"(a[3]), "r"(b[0]), "r"(b[1]));
}
__device__ __forceinline__ uint32_t pkh2(float x, float y) {
    __half2 h = __floats2half2_rn(x, y);
    return reinterpret_cast<uint32_t&>(h);
}
__device__ __forceinline__ uint32_t ex2h2(uint32_t x) {
    uint32_t r;
    asm("ex2.approx.f16x2 %0, %1;" : "=r"(r) : "r"(x));
    return r;
}
__device__ __forceinline__ uint32_t smem_u32(const void* p) {
    uint32_t a;
    asm("{ .reg .u64 t; cvta.to.shared.u64 t, %1; cvt.u32.u64 %0, t; }"
        : "=r"(a) : "l"(p));
    return a;
}
__device__ __forceinline__ void ldsm_x4(uint32_t r[4], uint32_t addr) {
    asm volatile("ldmatrix.sync.aligned.m8n8.x4.shared.b16 {%0,%1,%2,%3}, [%4];"
                 : "=r"(r[0]), "=r"(r[1]), "=r"(r[2]), "=r"(r[3]) : "r"(addr));
}
__device__ __forceinline__ void ldsm_x4t(uint32_t r[4], uint32_t addr) {
    asm volatile("ldmatrix.sync.aligned.m8n8.x4.trans.shared.b16 {%0,%1,%2,%3}, [%4];"
                 : "=r"(r[0]), "=r"(r[1]), "=r"(r[2]), "=r"(r[3]) : "r"(addr));
}
__device__ __forceinline__ void cpa16(uint32_t saddr, const void* g) {
    asm volatile("cp.async.ca.shared.global [%0], [%1], 16;"
                 :: "r"(saddr), "l"(g) : "memory");
}
#define CP_COMMIT() asm volatile("cp.async.commit_group;" ::: "memory")
#define CP_WAIT(n)  asm volatile("cp.async.wait_group %0;" :: "n"(n) : "memory")

// ===========================================================================
// Fused fp32 -> fp16 quantize; 4 independent float4 per thread (MLP=4).
// total quads = 2162688 = 2112 CTAs * 256 thr * 4.
// ===========================================================================
#define N4_X  (MROWS*CDIM/4)
#define N4_WQ (QKVO*CDIM/4)
#define N4_WP (CDIM*CDIM/4)
__global__ __launch_bounds__(256)
void quant_all(const float* __restrict__ x, const float* __restrict__ wq,
               const float* __restrict__ wp)
{
    const int i0 = (blockIdx.x * 256 + threadIdx.x) * 4;
#pragma unroll
    for (int u = 0; u < 4; ++u) {
        int j = i0 + u;
        const float* src;
        __half* dst;
        if (j < N4_X)                 { src = x;  dst = g_x; }
        else if ((j -= N4_X) < N4_WQ) { src = wq; dst = g_wq; }
        else                          { j -= N4_WQ; src = wp; dst = g_wp; }
        float4 v = *(const float4*)(src + 4 * (size_t)j);
        uint2 h;
        h.x = pkh2(v.x, v.y);
        h.y = pkh2(v.z, v.w);
        *(uint2*)(dst + 4 * (size_t)j) = h;
    }
}

// ===========================================================================
// fp16 HMMA GEMM (unchanged from R15): MT x 128 tile, KCH=64, 3-stage
// cp.async pipeline, paired-B ldsm_x4.
// MODE 0: A=g_x, B=g_wq; epilogue -> fp16 q(log2-scaled)/k/v in [B,H,N,D].
// MODE 1: A=g_att, B=g_wp; fp32 store to out.
// ===========================================================================
template <int MODE, int MT>
__global__ __launch_bounds__(256, 2)
void gemm_hmma(const float* __restrict__ bias, float* __restrict__ out)
{
    constexpr int MI     = MT / 32;
    constexpr int ATILE  = MT * GRS;
    constexpr int STG_SZ = (MT + 128) * GRS;
    constexpr int CPT    = (MT + 128) * 8 / 256;

    extern __shared__ char smg[];
    const uint32_t smu = smem_u32(smg);

    const __half* Asrc = (MODE == 0) ? g_x  : g_att;
    const __half* Bsrc = (MODE == 0) ? g_wq : g_wp;

    const int tid  = threadIdx.x;
    const int wid  = tid >> 5;
    const int lane = tid & 31;
    const int g    = lane >> 2;
    const int t    = lane & 3;
    const int wm   = wid >> 2;
    const int wn   = wid & 3;
    const int m0   = blockIdx.y * MT;
    const int n0   = blockIdx.x * 128;

    const int aRow = (lane & 15);
    const int aCol = (lane >> 4) << 4;
    const int pRow = (lane & 7) + 8 * ((lane >> 4) & 1);
    const int pCol = ((lane >> 3) & 1) << 4;

    const size_t baseA = (size_t)m0 * KDIM;
    const size_t baseB = (size_t)n0 * KDIM;

    auto load_chunk = [&](int c, int stg) {
        const uint32_t sb = smu + stg * STG_SZ;
#pragma unroll
        for (int j = 0; j < CPT; ++j) {
            int i = tid + j * 256;
            if (i < MT * 8) {
                const int row = i >> 3;
                const int cb  = (i & 7) << 4;
                cpa16(sb + row * GRS + cb,
                      (const char*)(Asrc + baseA + (size_t)row * KDIM
                                    + c * KCH + (cb >> 1)));
            } else {
                i -= MT * 8;
                const int row = i >> 3;
                const int cb  = (i & 7) << 4;
                cpa16(sb + ATILE + row * GRS + cb,
                      (const char*)(Bsrc + baseB + (size_t)row * KDIM
                                    + c * KCH + (cb >> 1)));
            }
        }
    };

    float acc[MI][4][4];
#pragma unroll
    for (int mi = 0; mi < MI; ++mi)
#pragma unroll
        for (int ni = 0; ni < 4; ++ni)
#pragma unroll
            for (int j = 0; j < 4; ++j) acc[mi][ni][j] = 0.0f;

    load_chunk(0, 0); CP_COMMIT();
    load_chunk(1, 1); CP_COMMIT();

    for (int c = 0; c < NCH; ++c) {
        const int cur = c % 3;
        if (c + 1 < NCH) { CP_WAIT(1); } else { CP_WAIT(0); }
        __syncthreads();
        if (c + 2 < NCH) { load_chunk(c + 2, (c + 2) % 3); CP_COMMIT(); }

        const uint32_t uA = smu + cur * STG_SZ;
        const uint32_t uB = uA + ATILE;

#pragma unroll
        for (int ks = 0; ks < 4; ++ks) {
            uint32_t af[MI][4];
#pragma unroll
            for (int mi = 0; mi < MI; ++mi)
                ldsm_x4(af[mi], uA + ((MT/2) * wm + 16 * mi + aRow) * GRS
                                   + 32 * ks + aCol);
#pragma unroll
            for (int nj = 0; nj < 2; ++nj) {
                uint32_t bf[4];
                ldsm_x4(bf, uB + (32 * wn + 16 * nj + pRow) * GRS
                               + 32 * ks + pCol);
#pragma unroll
                for (int mi = 0; mi < MI; ++mi) {
                    mma16816h(acc[mi][2 * nj],     af[mi], bf);
                    mma16816h(acc[mi][2 * nj + 1], af[mi], bf + 2);
                }
            }
        }
    }

    // ---- epilogue ----
#pragma unroll
    for (int mi = 0; mi < MI; ++mi) {
#pragma unroll
        for (int ni = 0; ni < 4; ++ni) {
            const int r1 = m0 + (MT/2) * wm + 16 * mi + g;
            const int r2 = r1 + 8;
            const int cA = n0 + 32 * wn + 8 * ni + 2 * t;
            const float b0 = bias[cA], b1 = bias[cA + 1];
            float v00 = acc[mi][ni][0] + b0;
            float v01 = acc[mi][ni][1] + b1;
            float v10 = acc[mi][ni][2] + b0;
            float v11 = acc[mi][ni][3] + b1;
            if (MODE == 0) {
                const int which = cA / CDIM;
                const int cin   = cA - which * CDIM;
                const int h     = cin >> 6;
                const int d     = cin & 63;
                if (which == 0) { v00 *= QSCALE; v01 *= QSCALE;
                                  v10 *= QSCALE; v11 *= QSCALE; }
                __half* dst = (which == 0) ? g_q : (which == 1) ? g_k : g_v;
#pragma unroll
                for (int rr = 0; rr < 2; ++rr) {
                    const int row = rr ? r2 : r1;
                    const int bb = row >> 11, s = row & 2047;
                    const size_t off = (((size_t)(bb * NHEAD + h)) * SEQ + s) * HDIM + d;
                    *(uint32_t*)(dst + off) = pkh2(rr ? v10 : v00, rr ? v11 : v01);
                }
            } else {
                *(float2*)(out + (size_t)r1 * CDIM + cA) = make_float2(v00, v01);
                *(float2*)(out + (size_t)r2 * CDIM + cA) = make_float2(v10, v11);
            }
        }
    }
}

// ===========================================================================
// fp16 flash attention v5: log2-domain max-free softmax, ones-MMA row sums,
// 4-stage cp.async pipeline (prefetch distance 3, tail wait ladder),
// per-kb fused S -> ex2 -> PV (kb+1's S overlaps kb's PV in the scoreboard).
// smem: Q (18432) + 4 stages x (Kh|V) (18432) = 92160 B.
// ===========================================================================
__global__ __launch_bounds__(256, 2)
void attn_hmma()
{
    extern __shared__ char sma[];
    const uint32_t smb = smem_u32(sma);
    const uint32_t uQ  = smb;
    const uint32_t uST = smb + 18432;

    const int qt = blockIdx.x;
    const int bh = blockIdx.y;
    const int b  = bh / NHEAD;
    const int h  = bh - b * NHEAD;
    const int qs = qt * TQ;

    const int tid  = threadIdx.x;
    const int wid  = tid >> 5;
    const int lane = tid & 31;
    const int g    = lane >> 2;
    const int t    = lane & 3;

    const int aRow = (lane & 15);
    const int aCol = (lane >> 4) << 4;
    const int kRow4 = (lane & 7) + 8 * ((lane >> 4) & 1);
    const int kCol4 = ((lane >> 3) & 1) << 4;
    const int vRow4 = (lane & 7) + 8 * ((lane >> 3) & 1);
    const int vCol4 = ((lane >> 4) & 1) << 4;

    const size_t headOff = ((size_t)(b * NHEAD + h)) * SEQ * HDIM;
    const __half* qp = g_q + headOff;
    const __half* kvp[2] = { g_k + headOff, g_v + headOff };

    auto load_stage = [&](int kt, int stg) {
        const uint32_t base = uST + stg * ASTG;
        const int ks = kt * 64;
#pragma unroll
        for (int j = 0; j < 4; ++j) {
            const int i   = tid + j * 256;
            const int buf = i >> 9;
            const int rem = i & 511;
            const int row = rem >> 3;
            const int cb  = (rem & 7) << 4;
            const __half* src = kvp[buf] + (size_t)(ks + row) * HDIM;
            cpa16(base + buf * 9216 + row * RSB + cb, (const char*)src + cb);
        }
    };

    // ---- prologue: Q + stage 0 in group 0; stages 1,2 in groups 1,2 ----
    for (int i = tid; i < 1024; i += 256) {
        const int row = i >> 3;
        const int cb  = (i & 7) << 4;
        cpa16(uQ + row * RSB + cb,
              (const char*)(qp + (size_t)(qs + row) * HDIM) + cb);
    }
    load_stage(0, 0); CP_COMMIT();
    load_stage(1, 1); CP_COMMIT();
    load_stage(2, 2); CP_COMMIT();

    const uint32_t ones[2] = { 0x3C003C00u, 0x3C003C00u };

    float o[8][4];
    float ol[4] = {0.0f, 0.0f, 0.0f, 0.0f};
#pragma unroll
    for (int ni = 0; ni < 8; ++ni)
#pragma unroll
        for (int j = 0; j < 4; ++j) o[ni][j] = 0.0f;

    uint32_t qfr[4][4];

    const int NT = SEQ / 64;   // 32 (divisible by 4 stages)

    for (int kt = 0; kt < NT; ++kt) {
        if (kt + 2 < NT)      { CP_WAIT(2); }
        else if (kt + 1 < NT) { CP_WAIT(1); }
        else                  { CP_WAIT(0); }
        __syncthreads();
        if (kt + 3 < NT) { load_stage(kt + 3, (kt + 3) & 3); CP_COMMIT(); }

        if (kt == 0) {
#pragma unroll
            for (int ks4 = 0; ks4 < 4; ++ks4)
                ldsm_x4(qfr[ks4], uQ + (16 * wid + aRow) * RSB
                                     + 32 * ks4 + aCol);
        }

        const uint32_t uK = uST + (kt & 3) * ASTG;
        const uint32_t uV = uK + 9216;

        // ---- per-kb fused: S(kb) -> ex2 -> PV(kb) ----
#pragma unroll
        for (int kb = 0; kb < 4; ++kb) {
            float s2[2][4];
#pragma unroll
            for (int j = 0; j < 4; ++j) { s2[0][j] = 0.0f; s2[1][j] = 0.0f; }

#pragma unroll
            for (int ks4 = 0; ks4 < 4; ++ks4) {
                uint32_t kf[4];
                ldsm_x4(kf, uK + (16 * kb + kRow4) * RSB + 32 * ks4 + kCol4);
                mma16816h(s2[0], qfr[ks4], kf);
                mma16816h(s2[1], qfr[ks4], kf + 2);
            }

            uint32_t ph[4];
            ph[0] = ex2h2(pkh2(s2[0][0], s2[0][1]));
            ph[1] = ex2h2(pkh2(s2[0][2], s2[0][3]));
            ph[2] = ex2h2(pkh2(s2[1][0], s2[1][1]));
            ph[3] = ex2h2(pkh2(s2[1][2], s2[1][3]));

#pragma unroll
            for (int nj = 0; nj < 4; ++nj) {
                uint32_t vf[4];
                ldsm_x4t(vf, uV + (16 * kb + vRow4) * RSB + 32 * nj + vCol4);
                mma16816h(o[2 * nj],     ph, vf);
                mma16816h(o[2 * nj + 1], ph, vf + 2);
            }
            mma16816h(ol, ph, ones);
        }
    }

    // ---- epilogue: O / l -> fp16 g_att ----
    const float inv1 = 1.0f / ol[0];
    const float inv2 = 1.0f / ol[2];
    const int r1 = qs + 16 * wid + g;
    const int r2 = r1 + 8;
#pragma unroll
    for (int ni = 0; ni < 8; ++ni) {
        const int col = h * HDIM + 8 * ni + 2 * t;
        *(uint32_t*)(g_att + ((size_t)(b * SEQ + r1)) * CDIM + col) =
            pkh2(o[ni][0] * inv1, o[ni][1] * inv1);
        *(uint32_t*)(g_att + ((size_t)(b * SEQ + r2)) * CDIM + col) =
            pkh2(o[ni][2] * inv2, o[ni][3] * inv2);
    }
}

// ===========================================================================
extern "C" void kernel_launch(void* const* d_in, const int* in_sizes, int n_in,
                              void* d_out, int out_size)
{
    const float* x = nullptr; const float* w_qkv = nullptr;
    const float* b_qkv = nullptr; const float* w_proj = nullptr;
    const float* b_proj = nullptr;
    for (int i = 0; i < n_in; ++i) {
        switch (in_sizes[i]) {
            case MROWS*CDIM:     x      = (const float*)d_in[i]; break;
            case QKVO*CDIM:      w_qkv  = (const float*)d_in[i]; break;
            case QKVO:           b_qkv  = (const float*)d_in[i]; break;
            case CDIM*CDIM:      w_proj = (const float*)d_in[i]; break;
            case CDIM:           b_proj = (const float*)d_in[i]; break;
            default: break;
        }
    }
    float* out = (float*)d_out;
    (void)out_size;

    const int GSM0 = 3 * 256 * GRS;           // 110592 (MT=128)
    const int GSM1 = 3 * 192 * GRS;           //  82944 (MT=64)
    const int ASM  = 18432 + 4 * ASTG;        //  92160
    cudaFuncSetAttribute((const void*)gemm_hmma<0,128>,
                         cudaFuncAttributeMaxDynamicSharedMemorySize, GSM0);
    cudaFuncSetAttribute((const void*)gemm_hmma<1,64>,
                         cudaFuncAttributeMaxDynamicSharedMemorySize, GSM1);
    cudaFuncSetAttribute((const void*)attn_hmma,
                         cudaFuncAttributeMaxDynamicSharedMemorySize, ASM);

    // 0) quantize all inputs to fp16 (exact-size grid, MLP=4)
    quant_all<<<2112, 256>>>(x, w_qkv, w_proj);

    // 1) QKV projection -> fp16 q(log2-scaled)/k/v
    dim3 g1(QKVO / 128, MROWS / 128);   // (18, 64)
    gemm_hmma<0,128><<<g1, 256, GSM0>>>(b_qkv, nullptr);

    // 2) fp16 flash attention (4-stage pipeline, fused kb loop) -> g_att
    dim3 g2(SEQ / TQ, BATCH * NHEAD);   // (16, 48)
    attn_hmma<<<g2, 256, ASM>>>();

    // 3) output projection (64-row M tiles) -> d_out
    dim3 g3(CDIM / 128, MROWS / 64);    // (6, 128)
    gemm_hmma<1,64><<<g3, 256, GSM1>>>(b_proj, out);
}